// round 7
// baseline (speedup 1.0000x reference)
#include <cuda_runtime.h>

// EffectiveProbability: post = normalize(p * (CM @ c)) per pixel.
// Input row-normalizations cancel against the output normalization -> skipped.
//
// prior/current [8,21,512,512] f32, cm [21,21] f32, out [B*H*W,21] f32.
//
// R7: issue-count attack. Adjacent pixel pair (2t,2t+1) per thread:
//  - gmem loads are LDG.64 float2 (half the LDG issues, naturally packed)
//  - CM staged as duplicated (w,w) u64 -> one LDS.64 broadcast per fma.rn.f32x2
//  - 441 FFMA2 + 441 LDS.64 per pixel PAIR (~30% fewer issues than R6,
//    half the fma-pipe demand). f32x2 is IEEE fp32 per lane: rel_err identical.
//  - results unpacked once into R6's proven pixel-major smem staging
//    (rows t and 256+t, stride-21 conflict-free), coalesced flush.

#define NCLS 21
#define HWSHIFT 18              // H*W = 512*512 = 2^18
#define HWSZ (1 << HWSHIFT)
#define BLOCK 256
#define PPB (2 * BLOCK)         // 512 pixels per block; 512 | 2^18

typedef unsigned long long u64;

__device__ __forceinline__ u64 ffma2(u64 a, u64 b, u64 c) {
    u64 d; asm("fma.rn.f32x2 %0, %1, %2, %3;" : "=l"(d) : "l"(a), "l"(b), "l"(c));
    return d;
}
__device__ __forceinline__ u64 fmul2(u64 a, u64 b) {
    u64 d; asm("mul.rn.f32x2 %0, %1, %2;" : "=l"(d) : "l"(a), "l"(b));
    return d;
}
__device__ __forceinline__ u64 fadd2(u64 a, u64 b) {
    u64 d; asm("add.rn.f32x2 %0, %1, %2;" : "=l"(d) : "l"(a), "l"(b));
    return d;
}
__device__ __forceinline__ void unpack2(u64 v, float& lo, float& hi) {
    asm("mov.b64 {%0, %1}, %2;" : "=f"(lo), "=f"(hi) : "l"(v));
}
__device__ __forceinline__ u64 pack2(float lo, float hi) {
    u64 v; asm("mov.b64 %0, {%1, %2};" : "=l"(v) : "f"(lo), "f"(hi));
    return v;
}

__global__ __launch_bounds__(BLOCK)
void eff_prob_kernel(const float* __restrict__ prior,
                     const float* __restrict__ current,
                     const float* __restrict__ cm,
                     float* __restrict__ out,
                     int npix)
{
    __shared__ u64   s_cm2[NCLS * NCLS];     // duplicated pairs (w,w): 3528 B
    __shared__ float s_out[PPB * NCLS];      // pixel-major staging, 43008 B
    __shared__ float s_inv[PPB];

    const int tid = threadIdx.x;

    for (int i = tid; i < NCLS * NCLS; i += BLOCK) {
        const float w = cm[i];
        s_cm2[i] = pack2(w, w);
    }
    __syncthreads();

    const int blk_base = blockIdx.x * PPB;
    const int pA = blk_base + 2 * tid;        // even pixel; pB = pA + 1
    if (pA + 1 < npix) {
        const int b  = pA >> HWSHIFT;         // pair never straddles a batch (even/odd)
        const int hw = pA & (HWSZ - 1);
        const size_t base2 = (((size_t)b * NCLS << HWSHIFT) + hw) >> 1;  // in u64 units
        const u64* __restrict__ cp2 = (const u64*)current + base2;
        const u64* __restrict__ pp2 = (const u64*)prior + base2;

        // Front-batched coalesced LDG.64: 21 loads cover both pixels' current.
        u64 cv[NCLS];
        #pragma unroll
        for (int j = 0; j < NCLS; j++) cv[j] = cp2[(size_t)j << (HWSHIFT - 1)];

        // Prior prefetch ring, depth 2 (LDG.64 pairs).
        u64 p0 = pp2[0];
        u64 p1 = pp2[(size_t)1 << (HWSHIFT - 1)];

        u64 acc2 = 0;                         // packed (0.f, 0.f)
        float* soA = s_out + tid * NCLS;               // stride 21: conflict-free
        float* soB = s_out + (BLOCK + tid) * NCLS;

        #pragma unroll
        for (int i = 0; i < NCLS; i++) {
            const u64 pc = p0;
            p0 = p1;
            if (i + 2 < NCLS) p1 = pp2[(size_t)(i + 2) << (HWSHIFT - 1)];

            u64 s2 = 0;
            #pragma unroll
            for (int j = 0; j < NCLS; j++)
                s2 = ffma2(s_cm2[i * NCLS + j], cv[j], s2);   // LDS.64 bcast + FFMA2

            const u64 t2 = fmul2(pc, s2);
            float tA, tB; unpack2(t2, tA, tB);                // register-pair movs
            soA[i] = tA;
            soB[i] = tB;
            acc2 = fadd2(acc2, t2);
        }
        float aA, aB; unpack2(acc2, aA, aB);
        s_inv[tid]         = 1.0f / aA;
        s_inv[BLOCK + tid] = 1.0f / aB;
    } else if (pA < npix) {
        // Tail safety (never taken for npix = 2^21): scalar single pixel.
        const int b  = pA >> HWSHIFT;
        const int hw = pA & (HWSZ - 1);
        const size_t base = ((size_t)b * NCLS << HWSHIFT) + hw;
        float cv[NCLS];
        #pragma unroll
        for (int j = 0; j < NCLS; j++) cv[j] = current[base + ((size_t)j << HWSHIFT)];
        float acc = 0.0f;
        float* so = s_out + tid * NCLS;
        #pragma unroll
        for (int i = 0; i < NCLS; i++) {
            float s = 0.0f;
            #pragma unroll
            for (int j = 0; j < NCLS; j++) {
                float w, wdup; unpack2(s_cm2[i * NCLS + j], w, wdup);
                s = fmaf(w, cv[j], s);
            }
            const float t = prior[base + ((size_t)i << HWSHIFT)] * s;
            so[i] = t;
            acc += t;
        }
        s_inv[tid] = 1.0f / acc;
    }
    __syncthreads();

    // Flush [PPB, 21] tile linearly: fully coalesced stores.
    // Block-local pixel p: p = 2m   -> smem row m        (thread m, pixel A)
    //                      p = 2m+1 -> smem row 256 + m  (thread m, pixel B)
    const long out_base = (long)blk_base * NCLS;
    const int  valid    = min(PPB, npix - blk_base);
    const int  count    = valid * NCLS;
    for (int k = tid; k < count; k += BLOCK) {
        const int pix = k / NCLS;                     // magic-mul, no real div
        const int c   = k - pix * NCLS;
        const int row = ((pix & 1) ? BLOCK : 0) + (pix >> 1);
        out[out_base + k] = s_out[row * NCLS + c] * s_inv[row];
    }
}

extern "C" void kernel_launch(void* const* d_in, const int* in_sizes, int n_in,
                              void* d_out, int out_size)
{
    const float* prior   = (const float*)d_in[0];
    const float* current = (const float*)d_in[1];
    const float* cm      = (const float*)d_in[2];
    float*       out     = (float*)d_out;

    const int npix = in_sizes[0] / NCLS;   // B*H*W
    const int grid = (npix + PPB - 1) / PPB;
    eff_prob_kernel<<<grid, BLOCK>>>(prior, current, cm, out, npix);
}

// round 8
// speedup vs baseline: 1.2343x; 1.2343x over previous
#include <cuda_runtime.h>

// EffectiveProbability: post = normalize(p * (CM @ c)) per pixel.
// Input row-normalizations cancel against the output normalization -> skipped.
//
// prior/current [8,21,512,512] f32, cm [21,21] f32, out [B*H*W,21] f32.
//
// R8: merge the two validated wins, drop the poison.
//  - R1's property: ALL 84 gmem loads (cvA,cvB,pvA,pvB) front-batched before
//    the compute loop -> no in-loop DRAM dependency (the depth-2 prefetch
//    ring in R5-R7 under-covered ~400cyc latency and was the real regression).
//  - R5's property: dual scalar FFMA chains share each LDS.32 broadcast of
//    cm[i][j] -> 220 LDS/pixel instead of 441 (L1 62%->44% proven).
//  - scalar fp32 only (both f32x2 attempts regressed on ALU plumbing).
//  - pair (tid, tid+256): same batch (512 | 2^18), smem rows output-ordered.
//  - flush: incremental k/21 mapping (no div), coalesced STG.

#define NCLS 21
#define HWSHIFT 18              // H*W = 512*512 = 2^18
#define HWSZ (1 << HWSHIFT)
#define BLOCK 256
#define PPB (2 * BLOCK)         // 512 pixels per block; 512 | 2^18

__global__ __launch_bounds__(BLOCK, 2)
void eff_prob_kernel(const float* __restrict__ prior,
                     const float* __restrict__ current,
                     const float* __restrict__ cm,
                     float* __restrict__ out,
                     int npix)
{
    __shared__ float s_cm[NCLS * NCLS];
    __shared__ float s_out[PPB * NCLS];      // 43008 B, rows in output pixel order
    __shared__ float s_inv[PPB];

    const int tid = threadIdx.x;
    for (int i = tid; i < NCLS * NCLS; i += BLOCK) s_cm[i] = cm[i];
    __syncthreads();

    const int blk_base = blockIdx.x * PPB;
    const int pA = blk_base + tid;            // smem row tid
    const int pB = pA + BLOCK;                // smem row BLOCK+tid, same batch as pA

    if (pB < npix) {
        const int b  = pA >> HWSHIFT;
        const int hw = pA & (HWSZ - 1);
        const size_t base = ((size_t)b * NCLS << HWSHIFT) + hw;
        const float* __restrict__ cp = current + base;   // pixel B at +BLOCK elems
        const float* __restrict__ pp = prior + base;

        // Front-batch ALL gmem loads: 84 independent coalesced LDG.32.
        // Entire DRAM latency is absorbed here via MLP; the compute loop
        // below touches only registers and smem.
        float cvA[NCLS], cvB[NCLS], pvA[NCLS], pvB[NCLS];
        #pragma unroll
        for (int j = 0; j < NCLS; j++) {
            const size_t o = (size_t)j << HWSHIFT;
            cvA[j] = cp[o];
            cvB[j] = cp[o + BLOCK];
        }
        #pragma unroll
        for (int j = 0; j < NCLS; j++) {
            const size_t o = (size_t)j << HWSHIFT;
            pvA[j] = pp[o];
            pvB[j] = pp[o + BLOCK];
        }

        float accA = 0.0f, accB = 0.0f;
        float* soA = s_out + tid * NCLS;              // stride 21: conflict-free
        float* soB = s_out + (BLOCK + tid) * NCLS;

        #pragma unroll
        for (int i = 0; i < NCLS; i++) {
            float sA = 0.0f, sB = 0.0f;
            #pragma unroll
            for (int j = 0; j < NCLS; j++) {
                const float w = s_cm[i * NCLS + j];   // one LDS.32 broadcast, 2 FFMAs
                sA = fmaf(w, cvA[j], sA);
                sB = fmaf(w, cvB[j], sB);
            }
            const float tA = pvA[i] * sA;
            const float tB = pvB[i] * sB;
            soA[i] = tA;
            soB[i] = tB;
            accA += tA;
            accB += tB;
        }
        s_inv[tid]         = 1.0f / accA;
        s_inv[BLOCK + tid] = 1.0f / accB;
    } else if (pA < npix) {
        // Tail safety (never taken for npix = 2^21): single-pixel path.
        const int b  = pA >> HWSHIFT;
        const int hw = pA & (HWSZ - 1);
        const size_t base = ((size_t)b * NCLS << HWSHIFT) + hw;
        float cv[NCLS], pv[NCLS];
        #pragma unroll
        for (int j = 0; j < NCLS; j++) cv[j] = current[base + ((size_t)j << HWSHIFT)];
        #pragma unroll
        for (int j = 0; j < NCLS; j++) pv[j] = prior[base + ((size_t)j << HWSHIFT)];
        float acc = 0.0f;
        float* so = s_out + tid * NCLS;
        #pragma unroll
        for (int i = 0; i < NCLS; i++) {
            float s = 0.0f;
            #pragma unroll
            for (int j = 0; j < NCLS; j++) s = fmaf(s_cm[i * NCLS + j], cv[j], s);
            const float t = pv[i] * s;
            so[i] = t;
            acc += t;
        }
        s_inv[tid] = 1.0f / acc;
    }
    __syncthreads();

    // Flush [PPB, 21] tile linearly (rows are already in output pixel order).
    // Incremental k/21 tracking: step +256 = +12*21+4.
    const long out_base = (long)blk_base * NCLS;
    const int  valid    = min(PPB, npix - blk_base);
    const int  count    = valid * NCLS;
    int pix = tid / NCLS;            // one-time small division
    int c   = tid - pix * NCLS;
    for (int k = tid; k < count; k += BLOCK) {
        out[out_base + k] = s_out[k] * s_inv[pix];
        c += 4;                       // 256 mod 21 = 4
        pix += 12;                    // 256 / 21 = 12
        if (c >= NCLS) { c -= NCLS; pix++; }
    }
}

extern "C" void kernel_launch(void* const* d_in, const int* in_sizes, int n_in,
                              void* d_out, int out_size)
{
    const float* prior   = (const float*)d_in[0];
    const float* current = (const float*)d_in[1];
    const float* cm      = (const float*)d_in[2];
    float*       out     = (float*)d_out;

    const int npix = in_sizes[0] / NCLS;   // B*H*W
    const int grid = (npix + PPB - 1) / PPB;
    eff_prob_kernel<<<grid, BLOCK>>>(prior, current, cm, out, npix);
}

// round 9
// speedup vs baseline: 1.8998x; 1.5392x over previous
#include <cuda_runtime.h>

// EffectiveProbability: post = normalize(p * (CM @ c)) per pixel.
// Input row-normalizations cancel against the output normalization -> skipped.
//
// prior/current [8,21,512,512] f32, cm [21,21] f32, out [B*H*W,21] f32.
//
// R9: exactly R1 (the 116.8us best: 1 px/thread, all 42 gmem loads
// front-batched, in-register normalize, smem-staged coalesced flush) with ONE
// change: the confusion matrix moves from shared memory to __constant__
// memory. Fully-unrolled loops make every CM index compile-time -> warp-
// uniform constant address -> LDCU on the uniform-const port (floor 1,
// separate from the LSU/smem crossbar). This deletes the 441 LDS broadcasts
// per warp that dominated R1's issue stream and LSU pressure.
// CM is filled via cudaMemcpyToSymbolAsync (D2D, graph-capturable).

#define NCLS 21
#define HWSHIFT 18              // H*W = 512*512 = 2^18
#define HWSZ (1 << HWSHIFT)
#define BLOCK 256

__constant__ float c_cm[NCLS * NCLS];

__global__ __launch_bounds__(BLOCK)
void eff_prob_kernel(const float* __restrict__ prior,
                     const float* __restrict__ current,
                     float* __restrict__ out,
                     int npix)
{
    __shared__ float s_out[BLOCK * NCLS];

    const int tid = threadIdx.x;
    const int n = blockIdx.x * BLOCK + tid;
    if (n < npix) {
        const int b  = n >> HWSHIFT;
        const int hw = n & (HWSZ - 1);
        const size_t base = ((size_t)b * NCLS << HWSHIFT) + hw;
        const float* __restrict__ cp = current + base;
        const float* __restrict__ pp = prior + base;

        // Front-batched fully-coalesced loads: maximum MLP, no in-loop DRAM.
        float cv[NCLS];
        #pragma unroll
        for (int j = 0; j < NCLS; j++) cv[j] = cp[(size_t)j << HWSHIFT];
        float pv[NCLS];
        #pragma unroll
        for (int j = 0; j < NCLS; j++) pv[j] = pp[(size_t)j << HWSHIFT];

        float post[NCLS];
        float acc = 0.0f;
        #pragma unroll
        for (int i = 0; i < NCLS; i++) {
            float s = 0.0f;
            #pragma unroll
            for (int j = 0; j < NCLS; j++)
                s = fmaf(c_cm[i * NCLS + j], cv[j], s);   // LDCU (uniform port) + FFMA
            const float t = pv[i] * s;
            post[i] = t;
            acc += t;
        }
        const float inv = 1.0f / acc;

        // Stage into smem for coalesced global stores.
        // Write stride 21 words across the warp: gcd(21,32)=1 -> conflict-free.
        #pragma unroll
        for (int i = 0; i < NCLS; i++)
            s_out[tid * NCLS + i] = post[i] * inv;
    }
    __syncthreads();

    // Flush block tile [BLOCK, 21] linearly -> fully coalesced 128B stores.
    const long out_base = (long)blockIdx.x * BLOCK * NCLS;
    const int  valid    = min(BLOCK, npix - blockIdx.x * BLOCK);
    const int  count    = valid * NCLS;
    for (int i = tid; i < count; i += BLOCK)
        out[out_base + i] = s_out[i];
}

extern "C" void kernel_launch(void* const* d_in, const int* in_sizes, int n_in,
                              void* d_out, int out_size)
{
    const float* prior   = (const float*)d_in[0];
    const float* current = (const float*)d_in[1];
    const float* cm      = (const float*)d_in[2];
    float*       out     = (float*)d_out;

    // D2D copy into the constant bank; async -> graph-capturable memcpy node.
    cudaMemcpyToSymbolAsync(c_cm, cm, NCLS * NCLS * sizeof(float), 0,
                            cudaMemcpyDeviceToDevice, 0);

    const int npix = in_sizes[0] / NCLS;   // B*H*W
    const int grid = (npix + BLOCK - 1) / BLOCK;
    eff_prob_kernel<<<grid, BLOCK>>>(prior, current, out, npix);
}